// round 7
// baseline (speedup 1.0000x reference)
#include <cuda_runtime.h>
#include <cuda_fp16.h>
#include <cstdint>
#include <math.h>

#define NHW 1024
#define KDIM 256
#define NBT 64

// ---------------- scratch (device globals: allocation-guard-safe) -------------
__device__ __half g_qkv[(size_t)NBT * 768 * NHW];   // 96 MB  [bt][768][hw]
__device__ __half g_att[(size_t)NBT * NHW * 256];   // 32 MB  [bt][hw][256]
__device__ __half g_xh [(size_t)NBT * KDIM * NHW];  // 32 MB  [bt][k][hw]
__device__ __half g_wh [(size_t)(768 + 256) * KDIM];

// ---------------- helpers ------------------------------------------------------
__device__ __forceinline__ uint32_t smem_u32(const void* p) {
    uint32_t a;
    asm("{ .reg .u64 t; cvta.to.shared.u64 t, %1; cvt.u32.u64 %0, t; }" : "=r"(a) : "l"(p));
    return a;
}
__device__ __forceinline__ uint32_t packh2(float lo, float hi) {
    __half2 h = __floats2half2_rn(lo, hi);
    return *reinterpret_cast<uint32_t*>(&h);
}
__device__ __forceinline__ void cpa16(uint32_t dst, const void* src) {
    asm volatile("cp.async.cg.shared.global [%0], [%1], 16;" :: "r"(dst), "l"(src));
}
__device__ __forceinline__ void cpa_commit() { asm volatile("cp.async.commit_group;"); }
template<int N> __device__ __forceinline__ void cpa_wait() {
    asm volatile("cp.async.wait_group %0;" :: "n"(N));
}
#define LDSM_X4(r0, r1, r2, r3, addr) \
    asm volatile("ldmatrix.sync.aligned.m8n8.x4.shared.b16 {%0,%1,%2,%3}, [%4];" \
                 : "=r"(r0), "=r"(r1), "=r"(r2), "=r"(r3) : "r"(addr))
#define LDSM_X4_T(r0, r1, r2, r3, addr) \
    asm volatile("ldmatrix.sync.aligned.m8n8.x4.trans.shared.b16 {%0,%1,%2,%3}, [%4];" \
                 : "=r"(r0), "=r"(r1), "=r"(r2), "=r"(r3) : "r"(addr))
#define MMA16816(c, a, b0v, b1v) \
    asm volatile("mma.sync.aligned.m16n8k16.row.col.f32.f16.f16.f32 " \
                 "{%0,%1,%2,%3}, {%4,%5,%6,%7}, {%8,%9}, {%0,%1,%2,%3};" \
                 : "+f"((c)[0]), "+f"((c)[1]), "+f"((c)[2]), "+f"((c)[3]) \
                 : "r"((a)[0]), "r"((a)[1]), "r"((a)[2]), "r"((a)[3]), "r"(b0v), "r"(b1v))

// ---------------- tiny convert kernels -----------------------------------------
__global__ __launch_bounds__(256) void cvt_x_kernel(const float* __restrict__ x,
                                                    __half* __restrict__ xh) {
    const size_t i = ((size_t)blockIdx.x * 256 + threadIdx.x) * 4;
    float4 f = *(const float4*)(x + i);
    uint2 u;
    u.x = packh2(f.x, f.y); u.y = packh2(f.z, f.w);
    *(uint2*)(xh + i) = u;
}
__global__ __launch_bounds__(256) void cvt_w_kernel(const float* __restrict__ wq,
                                                    const float* __restrict__ wo,
                                                    __half* __restrict__ wh) {
    const size_t i = ((size_t)blockIdx.x * 256 + threadIdx.x) * 4;
    const float* src = (i < (size_t)768 * KDIM) ? (wq + i) : (wo + (i - (size_t)768 * KDIM));
    float4 f = *(const float4*)src;
    uint2 u;
    u.x = packh2(f.x, f.y); u.y = packh2(f.z, f.w);
    *(uint2*)(wh + i) = u;
}

// ---------------- GEMM: cp.async staged, B full-K resident ---------------------
// C[bt][m][n] = sum_k A[m][k] * B_bt[k][n] + bias[m]
#define AST 16384
#define SMEM_B_OFF 0
#define SMEM_A_OFF 65536
#define G_SMEM (65536 + 3 * AST)    // 112 KB

template<int M, int MODE>
__global__ __launch_bounds__(256, 2) void gemm_async_kernel(
    const __half* __restrict__ A, const __half* __restrict__ B,
    const float* __restrict__ bias, void* __restrict__ outv)
{
    extern __shared__ char smem[];
    const uint32_t sb = smem_u32(smem);

    const int tid  = threadIdx.x;
    const int lane = tid & 31;
    const int wid  = tid >> 5;
    const int wm   = wid >> 2;
    const int wn   = wid & 3;
    const int g8   = lane >> 2;
    const int t4   = lane & 3;

    const int bt = blockIdx.y;
    const int n0 = blockIdx.x * 128;

    auto stage_A = [&](int slot, int m0, int kc) {
        const int m   = tid >> 1;
        const int k16b = (tid & 1) * 4;
        const uint32_t dbase = sb + SMEM_A_OFF + slot * AST + (uint32_t)m * 128u;
        const __half* src = A + (size_t)(m0 + m) * KDIM + kc * 64;
        #pragma unroll
        for (int q = 0; q < 4; q++) {
            const int k16 = k16b + q;
            cpa16(dbase + (((uint32_t)k16 * 16u) ^ (((uint32_t)m & 7u) << 4)),
                  src + k16 * 8);
        }
    };

    if (MODE == 0) {
        const __half* Bb = B + (size_t)bt * KDIM * NHW;
        const int k = tid;
        const uint32_t dbase = sb + SMEM_B_OFF + (uint32_t)k * 256u;
        const __half* src = Bb + (size_t)k * NHW + n0;
        #pragma unroll
        for (int n16 = 0; n16 < 16; n16++)
            cpa16(dbase + (((uint32_t)n16 * 16u) ^ (((uint32_t)k & 7u) << 4)),
                  src + n16 * 8);
    } else {
        const __half* Bb = B + (size_t)bt * NHW * KDIM;
        const int n = tid >> 1;
        const int kb = (tid & 1) * 16;
        const uint32_t dbase = sb + SMEM_B_OFF + (uint32_t)n * 512u;
        const __half* src = Bb + (size_t)(n0 + n) * KDIM;
        #pragma unroll
        for (int q = 0; q < 16; q++) {
            const int k16 = kb + q;
            cpa16(dbase + (((uint32_t)k16 * 16u) ^ (((uint32_t)n & 7u) << 4)),
                  src + k16 * 8);
        }
    }
    stage_A(0, 0, 0); cpa_commit();
    stage_A(1, 0, 1); cpa_commit();
    stage_A(2, 0, 2); cpa_commit();

    const int am  = ((lane >> 3) & 1) * 8 + (lane & 7);
    const uint32_t aC = ((lane >> 4) & 1) * 16;
    const uint32_t aS = (uint32_t)(am & 7) << 4;
    const int bnl = ((lane >> 4) & 1) * 8 + (lane & 7);
    const uint32_t bC = ((lane >> 3) & 1) * 16;
    const uint32_t bS = (uint32_t)(bnl & 7) << 4;
    const int tk  = lane & 15;
    const int nc8 = ((lane >> 4) & 1) * 8;
    const uint32_t tS = ((uint32_t)lane & 7u) << 4;

    for (int mt = 0; mt < M / 128; mt++) {
        const int m0 = mt * 128;
        if (mt > 0) {
            __syncthreads();
            stage_A(0, m0, 0); cpa_commit();
            stage_A(1, m0, 1); cpa_commit();
            stage_A(2, m0, 2); cpa_commit();
        }

        float acc[4][4][4];
        #pragma unroll
        for (int i = 0; i < 4; i++)
            #pragma unroll
            for (int j = 0; j < 4; j++)
                #pragma unroll
                for (int c = 0; c < 4; c++) acc[i][j][c] = 0.f;

        #pragma unroll
        for (int kc = 0; kc < 4; kc++) {
            if (kc == 0) cpa_wait<2>();
            else if (kc == 3) cpa_wait<0>();
            else cpa_wait<1>();
            __syncthreads();
            if (kc == 1) { stage_A(0, m0, 3); cpa_commit(); }

            const uint32_t abase = sb + SMEM_A_OFF + (kc % 3) * AST;
            #pragma unroll
            for (int kk = 0; kk < 4; kk++) {
                uint32_t a[4][4];
                #pragma unroll
                for (int mf = 0; mf < 4; mf++)
                    LDSM_X4(a[mf][0], a[mf][1], a[mf][2], a[mf][3],
                            abase + (uint32_t)(wm * 64 + mf * 16 + am) * 128u
                                  + (((uint32_t)(kk * 32) + aC) ^ aS));
                uint32_t b[2][4];
                #pragma unroll
                for (int nfp = 0; nfp < 2; nfp++) {
                    if (MODE == 0) {
                        const uint32_t addr = sb + SMEM_B_OFF
                            + (uint32_t)(kc * 64 + kk * 16 + tk) * 256u
                            + (((uint32_t)((wn * 32 + nfp * 16 + nc8) * 2)) ^ tS);
                        LDSM_X4_T(b[nfp][0], b[nfp][1], b[nfp][2], b[nfp][3], addr);
                    } else {
                        const uint32_t addr = sb + SMEM_B_OFF
                            + (uint32_t)(wn * 32 + nfp * 16 + bnl) * 512u
                            + (((uint32_t)((kc * 64 + kk * 16) * 2) + bC) ^ bS);
                        LDSM_X4(b[nfp][0], b[nfp][1], b[nfp][2], b[nfp][3], addr);
                    }
                }
                #pragma unroll
                for (int mf = 0; mf < 4; mf++)
                    #pragma unroll
                    for (int nf = 0; nf < 4; nf++)
                        MMA16816(acc[mf][nf], a[mf],
                                 b[nf >> 1][(nf & 1) * 2], b[nf >> 1][(nf & 1) * 2 + 1]);
            }
        }

        #pragma unroll
        for (int mf = 0; mf < 4; mf++) {
            const int m = m0 + wm * 64 + mf * 16 + g8;
            const float bz0 = bias[m], bz1 = bias[m + 8];
            #pragma unroll
            for (int nf = 0; nf < 4; nf++) {
                const int n = n0 + wn * 32 + nf * 8 + 2 * t4;
                if (MODE == 0) {
                    __half* Oh = (__half*)outv + (size_t)bt * M * NHW;
                    *(__half2*)(Oh + (size_t)m * NHW + n) =
                        __floats2half2_rn(acc[mf][nf][0] + bz0, acc[mf][nf][1] + bz0);
                    *(__half2*)(Oh + (size_t)(m + 8) * NHW + n) =
                        __floats2half2_rn(acc[mf][nf][2] + bz1, acc[mf][nf][3] + bz1);
                } else {
                    float* Of = (float*)outv + (size_t)bt * M * NHW;
                    *(float2*)(Of + (size_t)m * NHW + n) =
                        make_float2(acc[mf][nf][0] + bz0, acc[mf][nf][1] + bz0);
                    *(float2*)(Of + (size_t)(m + 8) * NHW + n) =
                        make_float2(acc[mf][nf][2] + bz1, acc[mf][nf][3] + bz1);
                }
            }
        }
    }
}

// ---------------- temporal attention: broadcast lane mapping -------------------
// qkv fp16 [bt][768][hw]; att fp16 [bt][hw][256]
// block = (16-hw tile, head, b), 256 threads; warp w: hw = 2w + (lane>>4), i = lane&15
// smem: ks/vs [j][hw][32d] rows 64B (broadcast reads -> conflicts moot)
//       qs    [hw][i][32d] rows padded to 40 halves (80B) for i-strided reads
#define ATT_KV_BYTES (16 * 16 * 32 * 2)          // 16 KB each
#define ATT_Q_BYTES  (16 * 16 * 40 * 2)          // 20 KB
#define ATT_SMEM     (2 * ATT_KV_BYTES + ATT_Q_BYTES)

__device__ __forceinline__ float dot8(const float* q, uint4 u) {
    const __half2* p = (const __half2*)&u;
    float a = 0.f;
    #pragma unroll
    for (int c = 0; c < 4; c++) {
        float2 f = __half22float2(p[c]);
        a += q[2 * c] * f.x + q[2 * c + 1] * f.y;
    }
    return a;
}
__device__ __forceinline__ void axpy8(float* o, float p, uint4 u) {
    const __half2* v = (const __half2*)&u;
    #pragma unroll
    for (int c = 0; c < 4; c++) {
        float2 f = __half22float2(v[c]);
        o[2 * c] += p * f.x; o[2 * c + 1] += p * f.y;
    }
}

__global__ __launch_bounds__(256, 2) void attn_kernel(
    const __half* __restrict__ qkv, const float* __restrict__ rel,
    __half* __restrict__ att)
{
    extern __shared__ char asmem[];
    __half* ks = (__half*)asmem;
    __half* vs = (__half*)(asmem + ATT_KV_BYTES);
    __half* qs = (__half*)(asmem + 2 * ATT_KV_BYTES);

    const int tid  = threadIdx.x;
    const int hw0  = blockIdx.x * 16;
    const int head = blockIdx.y;
    const int b    = blockIdx.z;
    const int bt0  = b * 16;

    // stage Q, K, V; item u = (tz, j, dp, h8); uniform tz per iteration
    for (int u = tid; u < 1536; u += 256) {
        const int tz = u >> 9;              // 0=q, 1=k, 2=v
        const int it = u & 511;
        const int j  = it >> 5;
        const int dp = (it >> 1) & 15;
        const int h8 = (it & 1) * 8;
        const __half* src = qkv + ((size_t)(bt0 + j) * 768 + tz * 256 + head * 32 + 2 * dp) * NHW + hw0 + h8;
        uint4 lo = *(const uint4*)src;
        uint4 hi = *(const uint4*)(src + NHW);
        const __half* l = (const __half*)&lo;
        const __half* h = (const __half*)&hi;
        if (tz == 0) {
            #pragma unroll
            for (int t = 0; t < 8; t++)
                *(__half2*)&qs[((h8 + t) * 16 + j) * 40 + 2 * dp] = __halves2half2(l[t], h[t]);
        } else {
            __half* dst = (tz == 1) ? ks : vs;
            #pragma unroll
            for (int t = 0; t < 8; t++)
                *(__half2*)&dst[(j * 16 + h8 + t) * 32 + 2 * dp] = __halves2half2(l[t], h[t]);
        }
    }
    __syncthreads();

    const int w    = tid >> 5;
    const int lane = tid & 31;
    const int hw   = 2 * w + (lane >> 4);
    const int i    = lane & 15;
    const float scale = 0.1767766952966369f;   // 32^-0.5

    // q into registers (8 LDS.128, one-time)
    float qv[32];
    {
        const uint4* qr = (const uint4*)&qs[(hw * 16 + i) * 40];
        #pragma unroll
        for (int c = 0; c < 8; c++) {
            uint4 u = qr[c];
            const __half2* p = (const __half2*)&u;
            #pragma unroll
            for (int d = 0; d < 4; d++) {
                float2 f = __half22float2(p[d]);
                qv[c * 8 + 2 * d]     = f.x * scale;
                qv[c * 8 + 2 * d + 1] = f.y * scale;
            }
        }
    }

    const float* rp = rel + (head * 16 + i) * 16;
    float s[16];
    #pragma unroll
    for (int j = 0; j < 16; j++) {
        const uint4* kr = (const uint4*)&ks[(j * 16 + hw) * 32];
        uint4 u0 = kr[0], u1 = kr[1], u2 = kr[2], u3 = kr[3];
        s[j] = dot8(qv, u0) + dot8(qv + 8, u1) + dot8(qv + 16, u2) + dot8(qv + 24, u3)
             + rp[j];
    }

    float mx = s[0];
    #pragma unroll
    for (int j = 1; j < 16; j++) mx = fmaxf(mx, s[j]);
    float l = 0.f;
    #pragma unroll
    for (int j = 0; j < 16; j++) { s[j] = __expf(s[j] - mx); l += s[j]; }
    const float inv = 1.f / l;
    #pragma unroll
    for (int j = 0; j < 16; j++) s[j] *= inv;

    float o[32];
    #pragma unroll
    for (int d = 0; d < 32; d++) o[d] = 0.f;
    #pragma unroll
    for (int j = 0; j < 16; j++) {
        const uint4* vr = (const uint4*)&vs[(j * 16 + hw) * 32];
        uint4 u0 = vr[0], u1 = vr[1], u2 = vr[2], u3 = vr[3];
        const float p = s[j];
        axpy8(o, p, u0); axpy8(o + 8, p, u1); axpy8(o + 16, p, u2); axpy8(o + 24, p, u3);
    }

    __half* ob = att + ((size_t)(bt0 + i) * NHW + hw0 + hw) * 256 + head * 32;
    #pragma unroll
    for (int c = 0; c < 4; c++) {
        uint4 r;
        r.x = packh2(o[c * 8 + 0], o[c * 8 + 1]);
        r.y = packh2(o[c * 8 + 2], o[c * 8 + 3]);
        r.z = packh2(o[c * 8 + 4], o[c * 8 + 5]);
        r.w = packh2(o[c * 8 + 6], o[c * 8 + 7]);
        *(uint4*)(ob + c * 8) = r;
    }
}

extern "C" void kernel_launch(void* const* d_in, const int* in_sizes, int n_in,
                              void* d_out, int out_size)
{
    const float* x     = (const float*)d_in[0];
    const float* rel   = (const float*)d_in[1];
    const float* w_qkv = (const float*)d_in[2];
    const float* b_qkv = (const float*)d_in[3];
    const float* w_out = (const float*)d_in[4];
    const float* b_out = (const float*)d_in[5];
    float* y = (float*)d_out;

    __half *qkv = nullptr, *att = nullptr, *xh = nullptr, *wh = nullptr;
    cudaGetSymbolAddress((void**)&qkv, g_qkv);
    cudaGetSymbolAddress((void**)&att, g_att);
    cudaGetSymbolAddress((void**)&xh,  g_xh);
    cudaGetSymbolAddress((void**)&wh,  g_wh);

    cudaFuncSetAttribute(gemm_async_kernel<768, 0>, cudaFuncAttributeMaxDynamicSharedMemorySize, G_SMEM);
    cudaFuncSetAttribute(gemm_async_kernel<256, 1>, cudaFuncAttributeMaxDynamicSharedMemorySize, G_SMEM);
    cudaFuncSetAttribute(attn_kernel, cudaFuncAttributeMaxDynamicSharedMemorySize, ATT_SMEM);

    // Stage 0: fp16 conversions
    cvt_w_kernel<<<(768 + 256) * KDIM / 1024, 256>>>(w_qkv, w_out, wh);
    cvt_x_kernel<<<(int)((size_t)NBT * KDIM * NHW / 1024), 256>>>(x, xh);
    // Stage 1: QKV projection -> qkv fp16 [bt][768][hw]
    gemm_async_kernel<768, 0><<<dim3(NHW / 128, NBT), 256, G_SMEM>>>(wh, xh, b_qkv, qkv);
    // Stage 2: temporal attention -> att fp16 [bt][hw][256]
    attn_kernel<<<dim3(NHW / 16, 8, 4), 256, ATT_SMEM>>>(qkv, rel, att);
    // Stage 3: output projection -> y fp32 [bt][256][hw]
    gemm_async_kernel<256, 1><<<dim3(NHW / 128, NBT), 256, G_SMEM>>>(
        wh + (size_t)768 * KDIM, att, b_out, y);
}

// round 8
// speedup vs baseline: 1.1019x; 1.1019x over previous
#include <cuda_runtime.h>
#include <cuda_fp16.h>
#include <cstdint>
#include <math.h>

#define NHW 1024
#define KDIM 256
#define NBT 64

// ---------------- scratch (device globals: allocation-guard-safe) -------------
__device__ __half g_qkv[(size_t)NBT * 768 * NHW];   // 96 MB  [bt][768][hw]
__device__ __half g_att[(size_t)NBT * NHW * 256];   // 32 MB  [bt][hw][256]
__device__ __half g_xh [(size_t)NBT * KDIM * NHW];  // 32 MB  [bt][k][hw]
__device__ __half g_wh [(size_t)(768 + 256) * KDIM];

// ---------------- helpers ------------------------------------------------------
__device__ __forceinline__ uint32_t smem_u32(const void* p) {
    uint32_t a;
    asm("{ .reg .u64 t; cvta.to.shared.u64 t, %1; cvt.u32.u64 %0, t; }" : "=r"(a) : "l"(p));
    return a;
}
__device__ __forceinline__ uint32_t packh2(float lo, float hi) {
    __half2 h = __floats2half2_rn(lo, hi);
    return *reinterpret_cast<uint32_t*>(&h);
}
__device__ __forceinline__ void cpa16(uint32_t dst, const void* src) {
    asm volatile("cp.async.cg.shared.global [%0], [%1], 16;" :: "r"(dst), "l"(src));
}
__device__ __forceinline__ void cpa_commit() { asm volatile("cp.async.commit_group;"); }
template<int N> __device__ __forceinline__ void cpa_wait() {
    asm volatile("cp.async.wait_group %0;" :: "n"(N));
}
#define LDSM_X4(r0, r1, r2, r3, addr) \
    asm volatile("ldmatrix.sync.aligned.m8n8.x4.shared.b16 {%0,%1,%2,%3}, [%4];" \
                 : "=r"(r0), "=r"(r1), "=r"(r2), "=r"(r3) : "r"(addr))
#define LDSM_X4_T(r0, r1, r2, r3, addr) \
    asm volatile("ldmatrix.sync.aligned.m8n8.x4.trans.shared.b16 {%0,%1,%2,%3}, [%4];" \
                 : "=r"(r0), "=r"(r1), "=r"(r2), "=r"(r3) : "r"(addr))
#define MMA16816(c, a, b0v, b1v) \
    asm volatile("mma.sync.aligned.m16n8k16.row.col.f32.f16.f16.f32 " \
                 "{%0,%1,%2,%3}, {%4,%5,%6,%7}, {%8,%9}, {%0,%1,%2,%3};" \
                 : "+f"((c)[0]), "+f"((c)[1]), "+f"((c)[2]), "+f"((c)[3]) \
                 : "r"((a)[0]), "r"((a)[1]), "r"((a)[2]), "r"((a)[3]), "r"(b0v), "r"(b1v))

// ---------------- tiny convert kernels -----------------------------------------
__global__ __launch_bounds__(256) void cvt_x_kernel(const float* __restrict__ x,
                                                    __half* __restrict__ xh) {
    const size_t i = ((size_t)blockIdx.x * 256 + threadIdx.x) * 4;
    float4 f = *(const float4*)(x + i);
    uint2 u;
    u.x = packh2(f.x, f.y); u.y = packh2(f.z, f.w);
    *(uint2*)(xh + i) = u;
}
__global__ __launch_bounds__(256) void cvt_w_kernel(const float* __restrict__ wq,
                                                    const float* __restrict__ wo,
                                                    __half* __restrict__ wh) {
    const size_t i = ((size_t)blockIdx.x * 256 + threadIdx.x) * 4;
    const float* src = (i < (size_t)768 * KDIM) ? (wq + i) : (wo + (i - (size_t)768 * KDIM));
    float4 f = *(const float4*)src;
    uint2 u;
    u.x = packh2(f.x, f.y); u.y = packh2(f.z, f.w);
    *(uint2*)(wh + i) = u;
}

// ---------------- GEMM: cp.async staged, B full-K resident ---------------------
#define AST 16384
#define SMEM_B_OFF 0
#define SMEM_A_OFF 65536
#define G_SMEM (65536 + 3 * AST)    // 112 KB

template<int M, int MODE>
__global__ __launch_bounds__(256, 2) void gemm_async_kernel(
    const __half* __restrict__ A, const __half* __restrict__ B,
    const float* __restrict__ bias, void* __restrict__ outv)
{
    extern __shared__ char smem[];
    const uint32_t sb = smem_u32(smem);

    const int tid  = threadIdx.x;
    const int lane = tid & 31;
    const int wid  = tid >> 5;
    const int wm   = wid >> 2;
    const int wn   = wid & 3;
    const int g8   = lane >> 2;
    const int t4   = lane & 3;

    const int bt = blockIdx.y;
    const int n0 = blockIdx.x * 128;

    auto stage_A = [&](int slot, int m0, int kc) {
        const int m   = tid >> 1;
        const int k16b = (tid & 1) * 4;
        const uint32_t dbase = sb + SMEM_A_OFF + slot * AST + (uint32_t)m * 128u;
        const __half* src = A + (size_t)(m0 + m) * KDIM + kc * 64;
        #pragma unroll
        for (int q = 0; q < 4; q++) {
            const int k16 = k16b + q;
            cpa16(dbase + (((uint32_t)k16 * 16u) ^ (((uint32_t)m & 7u) << 4)),
                  src + k16 * 8);
        }
    };

    if (MODE == 0) {
        const __half* Bb = B + (size_t)bt * KDIM * NHW;
        const int k = tid;
        const uint32_t dbase = sb + SMEM_B_OFF + (uint32_t)k * 256u;
        const __half* src = Bb + (size_t)k * NHW + n0;
        #pragma unroll
        for (int n16 = 0; n16 < 16; n16++)
            cpa16(dbase + (((uint32_t)n16 * 16u) ^ (((uint32_t)k & 7u) << 4)),
                  src + n16 * 8);
    } else {
        const __half* Bb = B + (size_t)bt * NHW * KDIM;
        const int n = tid >> 1;
        const int kb = (tid & 1) * 16;
        const uint32_t dbase = sb + SMEM_B_OFF + (uint32_t)n * 512u;
        const __half* src = Bb + (size_t)(n0 + n) * KDIM;
        #pragma unroll
        for (int q = 0; q < 16; q++) {
            const int k16 = kb + q;
            cpa16(dbase + (((uint32_t)k16 * 16u) ^ (((uint32_t)n & 7u) << 4)),
                  src + k16 * 8);
        }
    }
    stage_A(0, 0, 0); cpa_commit();
    stage_A(1, 0, 1); cpa_commit();
    stage_A(2, 0, 2); cpa_commit();

    const int am  = ((lane >> 3) & 1) * 8 + (lane & 7);
    const uint32_t aC = ((lane >> 4) & 1) * 16;
    const uint32_t aS = (uint32_t)(am & 7) << 4;
    const int bnl = ((lane >> 4) & 1) * 8 + (lane & 7);
    const uint32_t bC = ((lane >> 3) & 1) * 16;
    const uint32_t bS = (uint32_t)(bnl & 7) << 4;
    const int tk  = lane & 15;
    const int nc8 = ((lane >> 4) & 1) * 8;
    const uint32_t tS = ((uint32_t)lane & 7u) << 4;

    for (int mt = 0; mt < M / 128; mt++) {
        const int m0 = mt * 128;
        if (mt > 0) {
            __syncthreads();
            stage_A(0, m0, 0); cpa_commit();
            stage_A(1, m0, 1); cpa_commit();
            stage_A(2, m0, 2); cpa_commit();
        }

        float acc[4][4][4];
        #pragma unroll
        for (int i = 0; i < 4; i++)
            #pragma unroll
            for (int j = 0; j < 4; j++)
                #pragma unroll
                for (int c = 0; c < 4; c++) acc[i][j][c] = 0.f;

        #pragma unroll
        for (int kc = 0; kc < 4; kc++) {
            if (kc == 0) cpa_wait<2>();
            else if (kc == 3) cpa_wait<0>();
            else cpa_wait<1>();
            __syncthreads();
            if (kc == 1) { stage_A(0, m0, 3); cpa_commit(); }

            const uint32_t abase = sb + SMEM_A_OFF + (kc % 3) * AST;
            #pragma unroll
            for (int kk = 0; kk < 4; kk++) {
                uint32_t a[4][4];
                #pragma unroll
                for (int mf = 0; mf < 4; mf++)
                    LDSM_X4(a[mf][0], a[mf][1], a[mf][2], a[mf][3],
                            abase + (uint32_t)(wm * 64 + mf * 16 + am) * 128u
                                  + (((uint32_t)(kk * 32) + aC) ^ aS));
                uint32_t b[2][4];
                #pragma unroll
                for (int nfp = 0; nfp < 2; nfp++) {
                    if (MODE == 0) {
                        const uint32_t addr = sb + SMEM_B_OFF
                            + (uint32_t)(kc * 64 + kk * 16 + tk) * 256u
                            + (((uint32_t)((wn * 32 + nfp * 16 + nc8) * 2)) ^ tS);
                        LDSM_X4_T(b[nfp][0], b[nfp][1], b[nfp][2], b[nfp][3], addr);
                    } else {
                        const uint32_t addr = sb + SMEM_B_OFF
                            + (uint32_t)(wn * 32 + nfp * 16 + bnl) * 512u
                            + (((uint32_t)((kc * 64 + kk * 16) * 2) + bC) ^ bS);
                        LDSM_X4(b[nfp][0], b[nfp][1], b[nfp][2], b[nfp][3], addr);
                    }
                }
                #pragma unroll
                for (int mf = 0; mf < 4; mf++)
                    #pragma unroll
                    for (int nf = 0; nf < 4; nf++)
                        MMA16816(acc[mf][nf], a[mf],
                                 b[nf >> 1][(nf & 1) * 2], b[nf >> 1][(nf & 1) * 2 + 1]);
            }
        }

        #pragma unroll
        for (int mf = 0; mf < 4; mf++) {
            const int m = m0 + wm * 64 + mf * 16 + g8;
            const float bz0 = bias[m], bz1 = bias[m + 8];
            #pragma unroll
            for (int nf = 0; nf < 4; nf++) {
                const int n = n0 + wn * 32 + nf * 8 + 2 * t4;
                if (MODE == 0) {
                    __half* Oh = (__half*)outv + (size_t)bt * M * NHW;
                    *(__half2*)(Oh + (size_t)m * NHW + n) =
                        __floats2half2_rn(acc[mf][nf][0] + bz0, acc[mf][nf][1] + bz0);
                    *(__half2*)(Oh + (size_t)(m + 8) * NHW + n) =
                        __floats2half2_rn(acc[mf][nf][2] + bz1, acc[mf][nf][3] + bz1);
                } else {
                    float* Of = (float*)outv + (size_t)bt * M * NHW;
                    *(float2*)(Of + (size_t)m * NHW + n) =
                        make_float2(acc[mf][nf][0] + bz0, acc[mf][nf][1] + bz0);
                    *(float2*)(Of + (size_t)(m + 8) * NHW + n) =
                        make_float2(acc[mf][nf][2] + bz1, acc[mf][nf][3] + bz1);
                }
            }
        }
    }
}

// ---------------- temporal attention via tensor cores --------------------------
// qkv fp16 [bt][768][hw]; att fp16 [bt][hw][256]
// block = 16 warps (512 thr) = 16 hw positions x 1 head; warp = one instance.
// Per-instance smem: Q [t][d] 16x(32 pad 40) halves, K same, Vt [d][j] 32x(16 pad 40).
#define AI_STRIDE 40                    // padded row: 80 B -> ldmatrix conflict-free
#define AI_Q 0
#define AI_K 1280
#define AI_V 2560
#define AI_BYTES 5120
#define ATT_REL_OFF (16 * AI_BYTES)     // 81920
#define ATT_SMEM (ATT_REL_OFF + 1024)

__global__ __launch_bounds__(512, 2) void attn_mma_kernel(
    const __half* __restrict__ qkv, const float* __restrict__ rel,
    __half* __restrict__ att)
{
    extern __shared__ char asmem[];
    const uint32_t sb = smem_u32(asmem);

    const int tid  = threadIdx.x;
    const int hw0  = blockIdx.x * 16;
    const int head = blockIdx.y;
    const int b    = blockIdx.z;
    const int bt0  = b * 16;

    // stage rel tile for this head (256 floats)
    if (tid < 256) ((float*)(asmem + ATT_REL_OFF))[tid] = rel[head * 256 + tid];

    // stage Q/K/V: item u = (tz, j, d, h8); 1 LDG.128 + 8 scalar STS scatter
    #pragma unroll
    for (int it = 0; it < 6; it++) {
        const int u  = it * 512 + tid;
        const int h8 = u & 1;
        const int d  = (u >> 1) & 31;
        const int j  = (u >> 6) & 15;
        const int tz = u >> 10;                        // 0=q,1=k,2=v
        const __half* src = qkv + ((size_t)(bt0 + j) * 768 + tz * 256 + head * 32 + d) * NHW
                          + hw0 + h8 * 8;
        uint4 v = *(const uint4*)src;
        const unsigned short* hv = (const unsigned short*)&v;
        uint32_t dst = (tz == 2)
            ? sb + AI_V + (uint32_t)d * (AI_STRIDE * 2) + (uint32_t)j * 2
            : sb + (uint32_t)tz * AI_K + (uint32_t)j * (AI_STRIDE * 2) + (uint32_t)d * 2;
        dst += (uint32_t)(h8 * 8) * AI_BYTES;
        #pragma unroll
        for (int t = 0; t < 8; t++)
            asm volatile("st.shared.u16 [%0], %1;"
                         :: "r"(dst + (uint32_t)t * AI_BYTES), "h"(hv[t]) : "memory");
    }
    __syncthreads();

    const int w    = tid >> 5;      // instance = hw
    const int lane = tid & 31;
    const int g8   = lane >> 2;
    const int t4   = lane & 3;
    const uint32_t ibase = sb + (uint32_t)w * AI_BYTES;

    // fragment lane geometry (identical patterns to GEMM kernel)
    const int am  = ((lane >> 3) & 1) * 8 + (lane & 7);
    const uint32_t aC = ((lane >> 4) & 1) * 16;
    const int bnl = ((lane >> 4) & 1) * 8 + (lane & 7);
    const uint32_t bC = ((lane >> 3) & 1) * 16;

    // ---- S = Q K^T (16x16x32): 4 MMAs ----
    float S[2][4] = {{0.f, 0.f, 0.f, 0.f}, {0.f, 0.f, 0.f, 0.f}};
    #pragma unroll
    for (int kd = 0; kd < 2; kd++) {
        uint32_t aQ[4], bK[4];
        LDSM_X4(aQ[0], aQ[1], aQ[2], aQ[3],
                ibase + AI_Q + (uint32_t)am * (AI_STRIDE * 2) + aC + kd * 32);
        LDSM_X4(bK[0], bK[1], bK[2], bK[3],
                ibase + AI_K + (uint32_t)bnl * (AI_STRIDE * 2) + bC + kd * 32);
        MMA16816(S[0], aQ, bK[0], bK[1]);
        MMA16816(S[1], aQ, bK[2], bK[3]);
    }

    // ---- softmax in C-fragment layout ----
    const float scale = 0.1767766952966369f;  // 32^-0.5
    const float* relS = (const float*)(asmem + ATT_REL_OFF);
    float s[2][4];
    #pragma unroll
    for (int ng = 0; ng < 2; ng++)
        #pragma unroll
        for (int q = 0; q < 4; q++) {
            const int row = g8 + (q >= 2 ? 8 : 0);
            const int col = ng * 8 + 2 * t4 + (q & 1);
            s[ng][q] = S[ng][q] * scale + relS[row * 16 + col];
        }
    float mx0 = fmaxf(fmaxf(s[0][0], s[0][1]), fmaxf(s[1][0], s[1][1]));
    float mx8 = fmaxf(fmaxf(s[0][2], s[0][3]), fmaxf(s[1][2], s[1][3]));
    mx0 = fmaxf(mx0, __shfl_xor_sync(0xFFFFFFFFu, mx0, 1));
    mx0 = fmaxf(mx0, __shfl_xor_sync(0xFFFFFFFFu, mx0, 2));
    mx8 = fmaxf(mx8, __shfl_xor_sync(0xFFFFFFFFu, mx8, 1));
    mx8 = fmaxf(mx8, __shfl_xor_sync(0xFFFFFFFFu, mx8, 2));
    #pragma unroll
    for (int ng = 0; ng < 2; ng++) {
        s[ng][0] = __expf(s[ng][0] - mx0);
        s[ng][1] = __expf(s[ng][1] - mx0);
        s[ng][2] = __expf(s[ng][2] - mx8);
        s[ng][3] = __expf(s[ng][3] - mx8);
    }
    float l0 = s[0][0] + s[0][1] + s[1][0] + s[1][1];
    float l8 = s[0][2] + s[0][3] + s[1][2] + s[1][3];
    l0 += __shfl_xor_sync(0xFFFFFFFFu, l0, 1);
    l0 += __shfl_xor_sync(0xFFFFFFFFu, l0, 2);
    l8 += __shfl_xor_sync(0xFFFFFFFFu, l8, 1);
    l8 += __shfl_xor_sync(0xFFFFFFFFu, l8, 2);
    const float il0 = 1.f / l0, il8 = 1.f / l8;
    #pragma unroll
    for (int ng = 0; ng < 2; ng++) {
        s[ng][0] *= il0; s[ng][1] *= il0;
        s[ng][2] *= il8; s[ng][3] *= il8;
    }

    // P -> A fragment (pure register packing: C layout == A layout)
    uint32_t aP[4];
    aP[0] = packh2(s[0][0], s[0][1]);   // row g8,   j 2t4..   (ng0)
    aP[1] = packh2(s[0][2], s[0][3]);   // row g8+8, j 2t4..   (ng0)
    aP[2] = packh2(s[1][0], s[1][1]);   // row g8,   j 8+2t4.. (ng1)
    aP[3] = packh2(s[1][2], s[1][3]);   // row g8+8             (ng1)

    // ---- O = P V (16x32x16): 4 MMAs ----
    float O[4][4];
    #pragma unroll
    for (int i = 0; i < 4; i++)
        #pragma unroll
        for (int c = 0; c < 4; c++) O[i][c] = 0.f;
    #pragma unroll
    for (int dgp = 0; dgp < 2; dgp++) {
        uint32_t bV[4];
        LDSM_X4(bV[0], bV[1], bV[2], bV[3],
                ibase + AI_V + (uint32_t)(dgp * 16 + bnl) * (AI_STRIDE * 2) + bC);
        MMA16816(O[dgp * 2],     aP, bV[0], bV[1]);
        MMA16816(O[dgp * 2 + 1], aP, bV[2], bV[3]);
    }

    // ---- store: rows g8 and g8+8, d = dg*8 + 2t4 ----
    __half* ob = att + ((size_t)(bt0 + g8) * NHW + hw0 + w) * 256 + head * 32 + 2 * t4;
    __half* ob8 = ob + (size_t)8 * NHW * 256;
    #pragma unroll
    for (int dg = 0; dg < 4; dg++) {
        *(__half2*)(ob  + dg * 8) = __floats2half2_rn(O[dg][0], O[dg][1]);
        *(__half2*)(ob8 + dg * 8) = __floats2half2_rn(O[dg][2], O[dg][3]);
    }
}

extern "C" void kernel_launch(void* const* d_in, const int* in_sizes, int n_in,
                              void* d_out, int out_size)
{
    const float* x     = (const float*)d_in[0];
    const float* rel   = (const float*)d_in[1];
    const float* w_qkv = (const float*)d_in[2];
    const float* b_qkv = (const float*)d_in[3];
    const float* w_out = (const float*)d_in[4];
    const float* b_out = (const float*)d_in[5];
    float* y = (float*)d_out;

    __half *qkv = nullptr, *att = nullptr, *xh = nullptr, *wh = nullptr;
    cudaGetSymbolAddress((void**)&qkv, g_qkv);
    cudaGetSymbolAddress((void**)&att, g_att);
    cudaGetSymbolAddress((void**)&xh,  g_xh);
    cudaGetSymbolAddress((void**)&wh,  g_wh);

    cudaFuncSetAttribute(gemm_async_kernel<768, 0>, cudaFuncAttributeMaxDynamicSharedMemorySize, G_SMEM);
    cudaFuncSetAttribute(gemm_async_kernel<256, 1>, cudaFuncAttributeMaxDynamicSharedMemorySize, G_SMEM);
    cudaFuncSetAttribute(attn_mma_kernel, cudaFuncAttributeMaxDynamicSharedMemorySize, ATT_SMEM);

    // Stage 0: fp16 conversions
    cvt_w_kernel<<<(768 + 256) * KDIM / 1024, 256>>>(w_qkv, w_out, wh);
    cvt_x_kernel<<<(int)((size_t)NBT * KDIM * NHW / 1024), 256>>>(x, xh);
    // Stage 1: QKV projection -> qkv fp16 [bt][768][hw]
    gemm_async_kernel<768, 0><<<dim3(NHW / 128, NBT), 256, G_SMEM>>>(wh, xh, b_qkv, qkv);
    // Stage 2: temporal attention (tensor-core) -> att fp16 [bt][hw][256]
    attn_mma_kernel<<<dim3(NHW / 16, 8, 4), 512, ATT_SMEM>>>(qkv, rel, att);
    // Stage 3: output projection -> y fp32 [bt][256][hw]
    gemm_async_kernel<256, 1><<<dim3(NHW / 128, NBT), 256, G_SMEM>>>(
        wh + (size_t)768 * KDIM, att, b_out, y);
}

// round 9
// speedup vs baseline: 1.1282x; 1.0239x over previous
#include <cuda_runtime.h>
#include <cuda_fp16.h>
#include <cstdint>
#include <math.h>

#define NHW 1024
#define KDIM 256
#define NBT 64

// ---------------- scratch (device globals: allocation-guard-safe) -------------
__device__ __half g_qkv[(size_t)NBT * 768 * NHW];   // 96 MB  [bt][768][hw]
__device__ __half g_att[(size_t)NBT * NHW * 256];   // 32 MB  [bt][hw][256]
__device__ __half g_xh [(size_t)NBT * KDIM * NHW];  // 32 MB  [bt][k][hw]
__device__ __half g_wh [(size_t)(768 + 256) * KDIM];

// ---------------- helpers ------------------------------------------------------
__device__ __forceinline__ uint32_t smem_u32(const void* p) {
    uint32_t a;
    asm("{ .reg .u64 t; cvta.to.shared.u64 t, %1; cvt.u32.u64 %0, t; }" : "=r"(a) : "l"(p));
    return a;
}
__device__ __forceinline__ uint32_t packh2(float lo, float hi) {
    __half2 h = __floats2half2_rn(lo, hi);
    return *reinterpret_cast<uint32_t*>(&h);
}
__device__ __forceinline__ uint32_t prmt(uint32_t a, uint32_t b, uint32_t sel) {
    uint32_t r;
    asm("prmt.b32 %0, %1, %2, %3;" : "=r"(r) : "r"(a), "r"(b), "r"(sel));
    return r;
}
__device__ __forceinline__ void cpa16(uint32_t dst, const void* src) {
    asm volatile("cp.async.cg.shared.global [%0], [%1], 16;" :: "r"(dst), "l"(src));
}
__device__ __forceinline__ void cpa_commit() { asm volatile("cp.async.commit_group;"); }
template<int N> __device__ __forceinline__ void cpa_wait() {
    asm volatile("cp.async.wait_group %0;" :: "n"(N));
}
#define LDSM_X4(r0, r1, r2, r3, addr) \
    asm volatile("ldmatrix.sync.aligned.m8n8.x4.shared.b16 {%0,%1,%2,%3}, [%4];" \
                 : "=r"(r0), "=r"(r1), "=r"(r2), "=r"(r3) : "r"(addr))
#define LDSM_X4_T(r0, r1, r2, r3, addr) \
    asm volatile("ldmatrix.sync.aligned.m8n8.x4.trans.shared.b16 {%0,%1,%2,%3}, [%4];" \
                 : "=r"(r0), "=r"(r1), "=r"(r2), "=r"(r3) : "r"(addr))
#define MMA16816(c, a, b0v, b1v) \
    asm volatile("mma.sync.aligned.m16n8k16.row.col.f32.f16.f16.f32 " \
                 "{%0,%1,%2,%3}, {%4,%5,%6,%7}, {%8,%9}, {%0,%1,%2,%3};" \
                 : "+f"((c)[0]), "+f"((c)[1]), "+f"((c)[2]), "+f"((c)[3]) \
                 : "r"((a)[0]), "r"((a)[1]), "r"((a)[2]), "r"((a)[3]), "r"(b0v), "r"(b1v))

// ---------------- tiny convert kernels -----------------------------------------
__global__ __launch_bounds__(256) void cvt_x_kernel(const float* __restrict__ x,
                                                    __half* __restrict__ xh) {
    const size_t i = ((size_t)blockIdx.x * 256 + threadIdx.x) * 4;
    float4 f = *(const float4*)(x + i);
    uint2 u;
    u.x = packh2(f.x, f.y); u.y = packh2(f.z, f.w);
    *(uint2*)(xh + i) = u;
}
__global__ __launch_bounds__(256) void cvt_w_kernel(const float* __restrict__ wq,
                                                    const float* __restrict__ wo,
                                                    __half* __restrict__ wh) {
    const size_t i = ((size_t)blockIdx.x * 256 + threadIdx.x) * 4;
    const float* src = (i < (size_t)768 * KDIM) ? (wq + i) : (wo + (i - (size_t)768 * KDIM));
    float4 f = *(const float4*)src;
    uint2 u;
    u.x = packh2(f.x, f.y); u.y = packh2(f.z, f.w);
    *(uint2*)(wh + i) = u;
}

// ---------------- GEMM: cp.async staged, B full-K resident ---------------------
#define AST 16384
#define SMEM_B_OFF 0
#define SMEM_A_OFF 65536
#define G_SMEM (65536 + 3 * AST)    // 112 KB

template<int M, int MODE>
__global__ __launch_bounds__(256, 2) void gemm_async_kernel(
    const __half* __restrict__ A, const __half* __restrict__ B,
    const float* __restrict__ bias, void* __restrict__ outv)
{
    extern __shared__ char smem[];
    const uint32_t sb = smem_u32(smem);

    const int tid  = threadIdx.x;
    const int lane = tid & 31;
    const int wid  = tid >> 5;
    const int wm   = wid >> 2;
    const int wn   = wid & 3;
    const int g8   = lane >> 2;
    const int t4   = lane & 3;

    const int bt = blockIdx.y;
    const int n0 = blockIdx.x * 128;

    auto stage_A = [&](int slot, int m0, int kc) {
        const int m   = tid >> 1;
        const int k16b = (tid & 1) * 4;
        const uint32_t dbase = sb + SMEM_A_OFF + slot * AST + (uint32_t)m * 128u;
        const __half* src = A + (size_t)(m0 + m) * KDIM + kc * 64;
        #pragma unroll
        for (int q = 0; q < 4; q++) {
            const int k16 = k16b + q;
            cpa16(dbase + (((uint32_t)k16 * 16u) ^ (((uint32_t)m & 7u) << 4)),
                  src + k16 * 8);
        }
    };

    if (MODE == 0) {
        const __half* Bb = B + (size_t)bt * KDIM * NHW;
        const int k = tid;
        const uint32_t dbase = sb + SMEM_B_OFF + (uint32_t)k * 256u;
        const __half* src = Bb + (size_t)k * NHW + n0;
        #pragma unroll
        for (int n16 = 0; n16 < 16; n16++)
            cpa16(dbase + (((uint32_t)n16 * 16u) ^ (((uint32_t)k & 7u) << 4)),
                  src + n16 * 8);
    } else {
        const __half* Bb = B + (size_t)bt * NHW * KDIM;
        const int n = tid >> 1;
        const int kb = (tid & 1) * 16;
        const uint32_t dbase = sb + SMEM_B_OFF + (uint32_t)n * 512u;
        const __half* src = Bb + (size_t)(n0 + n) * KDIM;
        #pragma unroll
        for (int q = 0; q < 16; q++) {
            const int k16 = kb + q;
            cpa16(dbase + (((uint32_t)k16 * 16u) ^ (((uint32_t)n & 7u) << 4)),
                  src + k16 * 8);
        }
    }
    stage_A(0, 0, 0); cpa_commit();
    stage_A(1, 0, 1); cpa_commit();
    stage_A(2, 0, 2); cpa_commit();

    const int am  = ((lane >> 3) & 1) * 8 + (lane & 7);
    const uint32_t aC = ((lane >> 4) & 1) * 16;
    const uint32_t aS = (uint32_t)(am & 7) << 4;
    const int bnl = ((lane >> 4) & 1) * 8 + (lane & 7);
    const uint32_t bC = ((lane >> 3) & 1) * 16;
    const uint32_t bS = (uint32_t)(bnl & 7) << 4;
    const int tk  = lane & 15;
    const int nc8 = ((lane >> 4) & 1) * 8;
    const uint32_t tS = ((uint32_t)lane & 7u) << 4;

    for (int mt = 0; mt < M / 128; mt++) {
        const int m0 = mt * 128;
        if (mt > 0) {
            __syncthreads();
            stage_A(0, m0, 0); cpa_commit();
            stage_A(1, m0, 1); cpa_commit();
            stage_A(2, m0, 2); cpa_commit();
        }

        float acc[4][4][4];
        #pragma unroll
        for (int i = 0; i < 4; i++)
            #pragma unroll
            for (int j = 0; j < 4; j++)
                #pragma unroll
                for (int c = 0; c < 4; c++) acc[i][j][c] = 0.f;

        #pragma unroll
        for (int kc = 0; kc < 4; kc++) {
            if (kc == 0) cpa_wait<2>();
            else if (kc == 3) cpa_wait<0>();
            else cpa_wait<1>();
            __syncthreads();
            if (kc == 1) { stage_A(0, m0, 3); cpa_commit(); }

            const uint32_t abase = sb + SMEM_A_OFF + (kc % 3) * AST;
            #pragma unroll
            for (int kk = 0; kk < 4; kk++) {
                uint32_t a[4][4];
                #pragma unroll
                for (int mf = 0; mf < 4; mf++)
                    LDSM_X4(a[mf][0], a[mf][1], a[mf][2], a[mf][3],
                            abase + (uint32_t)(wm * 64 + mf * 16 + am) * 128u
                                  + (((uint32_t)(kk * 32) + aC) ^ aS));
                uint32_t b[2][4];
                #pragma unroll
                for (int nfp = 0; nfp < 2; nfp++) {
                    if (MODE == 0) {
                        const uint32_t addr = sb + SMEM_B_OFF
                            + (uint32_t)(kc * 64 + kk * 16 + tk) * 256u
                            + (((uint32_t)((wn * 32 + nfp * 16 + nc8) * 2)) ^ tS);
                        LDSM_X4_T(b[nfp][0], b[nfp][1], b[nfp][2], b[nfp][3], addr);
                    } else {
                        const uint32_t addr = sb + SMEM_B_OFF
                            + (uint32_t)(wn * 32 + nfp * 16 + bnl) * 512u
                            + (((uint32_t)((kc * 64 + kk * 16) * 2) + bC) ^ bS);
                        LDSM_X4(b[nfp][0], b[nfp][1], b[nfp][2], b[nfp][3], addr);
                    }
                }
                #pragma unroll
                for (int mf = 0; mf < 4; mf++)
                    #pragma unroll
                    for (int nf = 0; nf < 4; nf++)
                        MMA16816(acc[mf][nf], a[mf],
                                 b[nf >> 1][(nf & 1) * 2], b[nf >> 1][(nf & 1) * 2 + 1]);
            }
        }

        #pragma unroll
        for (int mf = 0; mf < 4; mf++) {
            const int m = m0 + wm * 64 + mf * 16 + g8;
            const float bz0 = bias[m], bz1 = bias[m + 8];
            #pragma unroll
            for (int nf = 0; nf < 4; nf++) {
                const int n = n0 + wn * 32 + nf * 8 + 2 * t4;
                if (MODE == 0) {
                    __half* Oh = (__half*)outv + (size_t)bt * M * NHW;
                    *(__half2*)(Oh + (size_t)m * NHW + n) =
                        __floats2half2_rn(acc[mf][nf][0] + bz0, acc[mf][nf][1] + bz0);
                    *(__half2*)(Oh + (size_t)(m + 8) * NHW + n) =
                        __floats2half2_rn(acc[mf][nf][2] + bz1, acc[mf][nf][3] + bz1);
                } else {
                    float* Of = (float*)outv + (size_t)bt * M * NHW;
                    *(float2*)(Of + (size_t)m * NHW + n) =
                        make_float2(acc[mf][nf][0] + bz0, acc[mf][nf][1] + bz0);
                    *(float2*)(Of + (size_t)(m + 8) * NHW + n) =
                        make_float2(acc[mf][nf][2] + bz1, acc[mf][nf][3] + bz1);
                }
            }
        }
    }
}

// ---------------- temporal attention via tensor cores --------------------------
// qkv fp16 [bt][768][hw]; att fp16 [bt][hw][256]
// block = 16 warps (512 thr) = 16 hw positions x 1 head; warp = one instance.
// Per-instance smem: Q [t][d] 16x(32 pad 40), K same, Vt [d][j] 32x(16 pad 40).
// Staging: register 8x8 half-transpose (PRMT) -> STS.128, no scalar scatter.
#define AI_STRIDE 40
#define AI_Q 0
#define AI_K 1280
#define AI_V 2560
#define AI_BYTES 5120
#define ATT_REL_OFF (16 * AI_BYTES)     // 81920
#define ATT_SMEM (ATT_REL_OFF + 1024)

// transpose 8x8 halves held in 8 uint4 (in[s] = 8 halves along minor axis)
// out[t] = uint4 of halves {in[0][t], in[1][t], ..., in[7][t]}
__device__ __forceinline__ void htr8x8(const uint4* in, uint4* out) {
    const uint32_t* w = (const uint32_t*)in;   // w[s*4 + (t>>1)]
    #pragma unroll
    for (int t = 0; t < 8; t++) {
        const uint32_t sel = (t & 1) ? 0x7632u : 0x5410u;
        const int c = t >> 1;
        out[t].x = prmt(w[0 * 4 + c], w[1 * 4 + c], sel);
        out[t].y = prmt(w[2 * 4 + c], w[3 * 4 + c], sel);
        out[t].z = prmt(w[4 * 4 + c], w[5 * 4 + c], sel);
        out[t].w = prmt(w[6 * 4 + c], w[7 * 4 + c], sel);
    }
}

__global__ __launch_bounds__(512, 2) void attn_mma_kernel(
    const __half* __restrict__ qkv, const float* __restrict__ rel,
    __half* __restrict__ att)
{
    extern __shared__ char asmem[];
    const uint32_t sb = smem_u32(asmem);

    const int tid  = threadIdx.x;
    const int hw0  = blockIdx.x * 16;
    const int head = blockIdx.y;
    const int b    = blockIdx.z;
    const int bt0  = b * 16;

    // rel tile staged by upper threads (runs concurrently with QKV staging)
    if (tid >= 256) ((float*)(asmem + ATT_REL_OFF))[tid - 256] = rel[head * 256 + tid - 256];

    // ---- staging: 384 items, one per thread ----
    // items [0,256): Q/K. item bits: h8=b0, d8=b1..2, j=b3..6, tz=b7
    // items [256,384): V.  v bits:   h8=b0, j8=b1, d=b2..6
    if (tid < 384) {
        uint4 in[8], out[8];
        if (tid < 256) {
            const int h8 = tid & 1;
            const int d8 = (tid >> 1) & 3;
            const int j  = (tid >> 3) & 15;
            const int tz = tid >> 7;
            const __half* src = qkv + ((size_t)(bt0 + j) * 768 + tz * 256 + head * 32 + d8 * 8) * NHW
                              + hw0 + h8 * 8;
            #pragma unroll
            for (int dd = 0; dd < 8; dd++)
                in[dd] = *(const uint4*)(src + (size_t)dd * NHW);
            htr8x8(in, out);
            const uint32_t dbase = sb + (uint32_t)tz * 1280u + (uint32_t)j * (AI_STRIDE * 2)
                                 + (uint32_t)d8 * 16u + (uint32_t)(h8 * 8) * AI_BYTES;
            #pragma unroll
            for (int t = 0; t < 8; t++)
                *(uint4*)(asmem + (dbase - sb) + (uint32_t)t * AI_BYTES) = out[t];
        } else {
            const int v  = tid - 256;
            const int h8 = v & 1;
            const int j8 = (v >> 1) & 1;
            const int d  = (v >> 2) & 31;
            const __half* src = qkv + ((size_t)(bt0 + j8 * 8) * 768 + 512 + head * 32 + d) * NHW
                              + hw0 + h8 * 8;
            #pragma unroll
            for (int jj = 0; jj < 8; jj++)
                in[jj] = *(const uint4*)(src + (size_t)jj * 768 * NHW);
            htr8x8(in, out);
            const uint32_t dbase = sb + AI_V + (uint32_t)d * (AI_STRIDE * 2)
                                 + (uint32_t)j8 * 16u + (uint32_t)(h8 * 8) * AI_BYTES;
            #pragma unroll
            for (int t = 0; t < 8; t++)
                *(uint4*)(asmem + (dbase - sb) + (uint32_t)t * AI_BYTES) = out[t];
        }
    }
    __syncthreads();

    const int w    = tid >> 5;      // instance = hw
    const int lane = tid & 31;
    const int g8   = lane >> 2;
    const int t4   = lane & 3;
    const uint32_t ibase = sb + (uint32_t)w * AI_BYTES;

    const int am  = ((lane >> 3) & 1) * 8 + (lane & 7);
    const uint32_t aC = ((lane >> 4) & 1) * 16;
    const int bnl = ((lane >> 4) & 1) * 8 + (lane & 7);
    const uint32_t bC = ((lane >> 3) & 1) * 16;

    // ---- S = Q K^T (16x16x32): 4 MMAs ----
    float S[2][4] = {{0.f, 0.f, 0.f, 0.f}, {0.f, 0.f, 0.f, 0.f}};
    #pragma unroll
    for (int kd = 0; kd < 2; kd++) {
        uint32_t aQ[4], bK[4];
        LDSM_X4(aQ[0], aQ[1], aQ[2], aQ[3],
                ibase + AI_Q + (uint32_t)am * (AI_STRIDE * 2) + aC + kd * 32);
        LDSM_X4(bK[0], bK[1], bK[2], bK[3],
                ibase + AI_K + (uint32_t)bnl * (AI_STRIDE * 2) + bC + kd * 32);
        MMA16816(S[0], aQ, bK[0], bK[1]);
        MMA16816(S[1], aQ, bK[2], bK[3]);
    }

    // ---- softmax in C-fragment layout ----
    const float scale = 0.1767766952966369f;  // 32^-0.5
    const float* relS = (const float*)(asmem + ATT_REL_OFF);
    float s[2][4];
    #pragma unroll
    for (int ng = 0; ng < 2; ng++)
        #pragma unroll
        for (int q = 0; q < 4; q++) {
            const int row = g8 + (q >= 2 ? 8 : 0);
            const int col = ng * 8 + 2 * t4 + (q & 1);
            s[ng][q] = S[ng][q] * scale + relS[row * 16 + col];
        }
    float mx0 = fmaxf(fmaxf(s[0][0], s[0][1]), fmaxf(s[1][0], s[1][1]));
    float mx8 = fmaxf(fmaxf(s[0][2], s[0][3]), fmaxf(s[1][2], s[1][3]));
    mx0 = fmaxf(mx0, __shfl_xor_sync(0xFFFFFFFFu, mx0, 1));
    mx0 = fmaxf(mx0, __shfl_xor_sync(0xFFFFFFFFu, mx0, 2));
    mx8 = fmaxf(mx8, __shfl_xor_sync(0xFFFFFFFFu, mx8, 1));
    mx8 = fmaxf(mx8, __shfl_xor_sync(0xFFFFFFFFu, mx8, 2));
    #pragma unroll
    for (int ng = 0; ng < 2; ng++) {
        s[ng][0] = __expf(s[ng][0] - mx0);
        s[ng][1] = __expf(s[ng][1] - mx0);
        s[ng][2] = __expf(s[ng][2] - mx8);
        s[ng][3] = __expf(s[ng][3] - mx8);
    }
    float l0 = s[0][0] + s[0][1] + s[1][0] + s[1][1];
    float l8 = s[0][2] + s[0][3] + s[1][2] + s[1][3];
    l0 += __shfl_xor_sync(0xFFFFFFFFu, l0, 1);
    l0 += __shfl_xor_sync(0xFFFFFFFFu, l0, 2);
    l8 += __shfl_xor_sync(0xFFFFFFFFu, l8, 1);
    l8 += __shfl_xor_sync(0xFFFFFFFFu, l8, 2);
    const float il0 = 1.f / l0, il8 = 1.f / l8;
    #pragma unroll
    for (int ng = 0; ng < 2; ng++) {
        s[ng][0] *= il0; s[ng][1] *= il0;
        s[ng][2] *= il8; s[ng][3] *= il8;
    }

    // P -> A fragment (pure register packing: C layout == A layout)
    uint32_t aP[4];
    aP[0] = packh2(s[0][0], s[0][1]);
    aP[1] = packh2(s[0][2], s[0][3]);
    aP[2] = packh2(s[1][0], s[1][1]);
    aP[3] = packh2(s[1][2], s[1][3]);

    // ---- O = P V (16x32x16): 4 MMAs ----
    float O[4][4];
    #pragma unroll
    for (int i = 0; i < 4; i++)
        #pragma unroll
        for (int c = 0; c < 4; c++) O[i][c] = 0.f;
    #pragma unroll
    for (int dgp = 0; dgp < 2; dgp++) {
        uint32_t bV[4];
        LDSM_X4(bV[0], bV[1], bV[2], bV[3],
                ibase + AI_V + (uint32_t)(dgp * 16 + bnl) * (AI_STRIDE * 2) + bC);
        MMA16816(O[dgp * 2],     aP, bV[0], bV[1]);
        MMA16816(O[dgp * 2 + 1], aP, bV[2], bV[3]);
    }

    // ---- store: rows g8 and g8+8, d = dg*8 + 2t4 ----
    __half* ob = att + ((size_t)(bt0 + g8) * NHW + hw0 + w) * 256 + head * 32 + 2 * t4;
    __half* ob8 = ob + (size_t)8 * NHW * 256;
    #pragma unroll
    for (int dg = 0; dg < 4; dg++) {
        *(__half2*)(ob  + dg * 8) = __floats2half2_rn(O[dg][0], O[dg][1]);
        *(__half2*)(ob8 + dg * 8) = __floats2half2_rn(O[dg][2], O[dg][3]);
    }
}

extern "C" void kernel_launch(void* const* d_in, const int* in_sizes, int n_in,
                              void* d_out, int out_size)
{
    const float* x     = (const float*)d_in[0];
    const float* rel   = (const float*)d_in[1];
    const float* w_qkv = (const float*)d_in[2];
    const float* b_qkv = (const float*)d_in[3];
    const float* w_out = (const float*)d_in[4];
    const float* b_out = (const float*)d_in[5];
    float* y = (float*)d_out;

    __half *qkv = nullptr, *att = nullptr, *xh = nullptr, *wh = nullptr;
    cudaGetSymbolAddress((void**)&qkv, g_qkv);
    cudaGetSymbolAddress((void**)&att, g_att);
    cudaGetSymbolAddress((void**)&xh,  g_xh);
    cudaGetSymbolAddress((void**)&wh,  g_wh);

    cudaFuncSetAttribute(gemm_async_kernel<768, 0>, cudaFuncAttributeMaxDynamicSharedMemorySize, G_SMEM);
    cudaFuncSetAttribute(gemm_async_kernel<256, 1>, cudaFuncAttributeMaxDynamicSharedMemorySize, G_SMEM);
    cudaFuncSetAttribute(attn_mma_kernel, cudaFuncAttributeMaxDynamicSharedMemorySize, ATT_SMEM);

    // Stage 0: fp16 conversions
    cvt_w_kernel<<<(768 + 256) * KDIM / 1024, 256>>>(w_qkv, w_out, wh);
    cvt_x_kernel<<<(int)((size_t)NBT * KDIM * NHW / 1024), 256>>>(x, xh);
    // Stage 1: QKV projection -> qkv fp16 [bt][768][hw]
    gemm_async_kernel<768, 0><<<dim3(NHW / 128, NBT), 256, G_SMEM>>>(wh, xh, b_qkv, qkv);
    // Stage 2: temporal attention (tensor-core) -> att fp16 [bt][hw][256]
    attn_mma_kernel<<<dim3(NHW / 16, 8, 4), 512, ATT_SMEM>>>(qkv, rel, att);
    // Stage 3: output projection -> y fp32 [bt][256][hw]
    gemm_async_kernel<256, 1><<<dim3(NHW / 128, NBT), 256, G_SMEM>>>(
        wh + (size_t)768 * KDIM, att, b_out, y);
}